// round 15
// baseline (speedup 1.0000x reference)
#include <cuda_runtime.h>
#include <cuda_fp16.h>
#include <math.h>
#include <cstdint>

#define H    128
#define KNB  48
#define LSEQ 2048
#define NTOK_MAX 4096

// ---------------- device scratch ----------------
__device__ float g_P1 [NTOK_MAX * H];
__device__ float g_P3 [NTOK_MAX * H];
__device__ float g_P11[NTOK_MAX * H];
__device__ float g_P13[NTOK_MAX * H];
__device__ float g_dh [NTOK_MAX * H];
// 6 weight mats, transposed [n][k], fp16 hi then fp16 lo (each 16384)
__device__ __half g_W[6 * 32768];

__device__ __forceinline__ float gelu_f(float x) {
    return 0.5f * x * (1.0f + erff(x * 0.70710678118654752f));
}

__device__ __forceinline__ uint32_t smem_u32(const void* p) {
    uint32_t a;
    asm("{ .reg .u64 t; cvta.to.shared.u64 t, %1; cvt.u32.u64 %0, t; }" : "=r"(a) : "l"(p));
    return a;
}

__device__ __forceinline__ void mma16816(float* c, const uint32_t* a,
                                         uint32_t b0, uint32_t b1) {
    asm volatile(
        "mma.sync.aligned.m16n8k16.row.col.f32.f16.f16.f32 "
        "{%0,%1,%2,%3}, {%4,%5,%6,%7}, {%8,%9}, {%0,%1,%2,%3};"
        : "+f"(c[0]), "+f"(c[1]), "+f"(c[2]), "+f"(c[3])
        : "r"(a[0]), "r"(a[1]), "r"(a[2]), "r"(a[3]), "r"(b0), "r"(b1));
}

#define LDSM4(r0, r1, r2, r3, addr) \
    asm volatile("ldmatrix.sync.aligned.m8n8.x4.shared.b16 {%0,%1,%2,%3}, [%4];" \
                 : "=r"(r0), "=r"(r1), "=r"(r2), "=r"(r3) : "r"(addr))

#define CP_COMMIT() asm volatile("cp.async.commit_group;" ::: "memory")
#define CP_WAIT0()  asm volatile("cp.async.wait_group 0;" ::: "memory")

// ---------------- smem layout (bytes) ----------------
#define LDA    136
#define STG_LD 130
#define SLAB  34816          // 128*136*2
#define SM_W0   0            // weight buf 0: hi slab + lo slab (69632)
#define SM_W1   69632        // weight buf 1 (also MODE0 staging late)
#define SM_A    139264       // activations: SINGLE fp16 slab (34816)
#define SM_NBR  174080       // 128 int
#define SM_MASK 174592       // 128 f
#define SM_B2   175104
#define SM_B3   175616
#define SM_G    176128
#define SM_BE   176640
#define SM_PAR  177152       // 1024 f = 4096
#define SMEM_MLP 181248

// ---------------- weight prep: transpose + fp16 hi/lo split ----------------
__global__ void k_wprep(const float* W1b, const float* W2, const float* W3,
                        const float* W11b, const float* W12, const float* W13) {
    int id = blockIdx.x * 256 + threadIdx.x;    // 6*16384
    int m = id >> 14, e = id & 16383;
    int n = e >> 7, k = e & 127;
    const float* srcs[6] = {W1b, W2, W3, W11b, W12, W13};
    float v = srcs[m][k * H + n];
    __half h = __float2half_rn(v);
    g_W[m * 32768 + e]         = h;
    g_W[m * 32768 + 16384 + e] = __float2half_rn(v - __half2float(h));
}

// async weight load (512 threads): 4096 x 16B
__device__ __forceinline__ void load_w_async(uint32_t smDst, int tid, int mat) {
    const char* src = (const char*)(g_W + (size_t)mat * 32768);
    #pragma unroll
    for (int it = 0; it < 8; it++) {
        int id = tid + it * 512;
        int hl = id >> 11, j = id & 2047;
        int n = j >> 4, kc = (j & 15) << 3;
        uint32_t dst = smDst + hl * SLAB + (uint32_t)((n * LDA + kc) * 2);
        asm volatile("cp.async.cg.shared.global [%0], [%1], 16;"
                     :: "r"(dst), "l"(src + (size_t)id * 16));
    }
}

// 2-pass GEMM (A fp16, W hi+lo): acc[4][8] += A(128x128) x W^T (warp: 32x32)
__device__ __forceinline__ void do_gemm(uint32_t wBase, uint32_t aBase, float acc[4][8],
                                        int rowbase, int colq, int lane) {
    int arow = rowbase + (lane & 15);
    int acol = (lane >> 4) << 3;
    uint32_t aOff = aBase + (uint32_t)((arow * LDA + acol) * 2);
    int nrow = colq * 32 + (lane & 7) + ((lane >> 4) << 3);
    int bcol = ((lane >> 3) & 1) << 3;
    uint32_t bOff = wBase + (uint32_t)((nrow * LDA + bcol) * 2);
    #pragma unroll 1
    for (int pass = 0; pass < 2; pass++) {
        uint32_t bB = bOff + ((pass == 1) ? SLAB : 0);
        #pragma unroll 1
        for (int ks = 0; ks < 8; ks++) {
            uint32_t a0[4], a1[4];
            LDSM4(a0[0], a0[1], a0[2], a0[3], aOff + ks * 32);
            LDSM4(a1[0], a1[1], a1[2], a1[3], aOff + 16 * LDA * 2 + ks * 32);
            #pragma unroll
            for (int ntp = 0; ntp < 2; ntp++) {
                uint32_t b0, b1, b2, b3;
                LDSM4(b0, b1, b2, b3, bB + ntp * 16 * LDA * 2 + ks * 32);
                mma16816(&acc[2 * ntp][0],     a0, b0, b1);
                mma16816(&acc[2 * ntp][4],     a1, b0, b1);
                mma16816(&acc[2 * ntp + 1][0], a0, b2, b3);
                mma16816(&acc[2 * ntp + 1][4], a1, b2, b3);
            }
        }
    }
}

// GELU(acc) -> A slab (fp16), for next layer's input
__device__ __forceinline__ void epi_act(char* sm, float acc[4][8],
                                        int rowbase, int colq, int gid, int tig) {
    #pragma unroll
    for (int nt = 0; nt < 4; nt++) {
        int col = colq * 32 + nt * 8 + 2 * tig;
        #pragma unroll
        for (int q = 0; q < 4; q++) {
            int row = rowbase + q * 8 + gid;
            __half2 h = __floats2half2_rn(gelu_f(acc[nt][q * 2]),
                                          gelu_f(acc[nt][q * 2 + 1]));
            *(uint32_t*)(sm + SM_A + (row * LDA + col) * 2) =
                *reinterpret_cast<uint32_t*>(&h);
        }
    }
}

// ---------------- fused 3-layer MLP over one 128-row tile (512 thr) ----------
// MODE 0: node messages -> masked per-token sums into g_dh (atomic)
// MODE 1: edge update -> +hE residual, row LN, write outE
template <int MODE>
__global__ void __launch_bounds__(512, 1) k_mlp(
    const float* __restrict__ hE, const int* __restrict__ Eidx,
    const float* __restrict__ bias2, const float* __restrict__ bias3,
    const float* __restrict__ lng, const float* __restrict__ lnb,
    const float* __restrict__ mattend, float* __restrict__ outE) {
    extern __shared__ char sm[];
    int*   snbr  = (int*)(sm + SM_NBR);
    float* smask = (float*)(sm + SM_MASK);
    float* sb2   = (float*)(sm + SM_B2);
    float* sb3   = (float*)(sm + SM_B3);
    float* sg    = (float*)(sm + SM_G);
    float* sbe   = (float*)(sm + SM_BE);
    float* spar  = (float*)(sm + SM_PAR);

    int tid = threadIdx.x, wid = tid >> 5, lane = tid & 31;
    int gid = lane >> 2, tig = lane & 3;
    int rowbase = (wid & 3) * 32;
    int colq = wid >> 2;
    int grow0 = blockIdx.x * 128;
    uint32_t smb = smem_u32(sm);

    load_w_async(smb + SM_W0, tid, MODE * 3 + 0);
    CP_COMMIT();

    if (tid < 128) {
        int gr = grow0 + tid;
        int t = gr / KNB;
        snbr[tid] = (t / LSEQ) * LSEQ + Eidx[gr];
        smask[tid] = (MODE == 0) ? mattend[gr] : 0.f;
        sb2[tid] = bias2[tid]; sb3[tid] = bias3[tid];
        sg[tid] = lng[tid];    sbe[tid] = lnb[tid];
    }

    // A <- fp16(hE tile)
    const float4* hE4 = reinterpret_cast<const float4*>(hE + (size_t)grow0 * H);
    #pragma unroll
    for (int it = 0; it < 8; it++) {
        int id = tid + it * 512;
        int rr = id >> 5, c4 = id & 31;
        float4 v = hE4[rr * 32 + c4];
        __half2 h01 = __floats2half2_rn(v.x, v.y);
        __half2 h23 = __floats2half2_rn(v.z, v.w);
        *(uint2*)(sm + SM_A + (rr * LDA + c4 * 4) * 2) =
            make_uint2(*reinterpret_cast<uint32_t*>(&h01),
                       *reinterpret_cast<uint32_t*>(&h23));
    }
    CP_WAIT0();
    __syncthreads();

    float acc[4][8];

    // ---- layer 1: acc init = P_center + P_nbr (exact fp32, from global) ----
    {
        const float* Padd = (MODE == 0) ? g_P1 : g_P11;
        const float* Pnbr = (MODE == 0) ? g_P3 : g_P13;
        int tokv[4], nbv[4];
        #pragma unroll
        for (int q = 0; q < 4; q++) {
            int row = rowbase + q * 8 + gid;
            tokv[q] = (grow0 + row) / KNB;
            nbv[q] = snbr[row];
        }
        #pragma unroll
        for (int nt = 0; nt < 4; nt++) {
            int col = colq * 32 + nt * 8 + 2 * tig;
            #pragma unroll
            for (int q = 0; q < 4; q++) {
                float2 a = *(const float2*)(Padd + (size_t)tokv[q] * H + col);
                float2 b = *(const float2*)(Pnbr + (size_t)nbv[q] * H + col);
                acc[nt][q * 2] = a.x + b.x; acc[nt][q * 2 + 1] = a.y + b.y;
            }
        }
    }
    load_w_async(smb + SM_W1, tid, MODE * 3 + 1);
    CP_COMMIT();
    do_gemm(smb + SM_W0, smb + SM_A, acc, rowbase, colq, lane);
    CP_WAIT0();
    __syncthreads();
    epi_act(sm, acc, rowbase, colq, gid, tig);
    __syncthreads();

    // ---- layer 2 ----
    #pragma unroll
    for (int nt = 0; nt < 4; nt++) {
        int col = colq * 32 + nt * 8 + 2 * tig;
        float b0 = sb2[col], b1 = sb2[col + 1];
        #pragma unroll
        for (int q = 0; q < 4; q++) { acc[nt][q * 2] = b0; acc[nt][q * 2 + 1] = b1; }
    }
    load_w_async(smb + SM_W0, tid, MODE * 3 + 2);
    CP_COMMIT();
    do_gemm(smb + SM_W1, smb + SM_A, acc, rowbase, colq, lane);
    CP_WAIT0();
    __syncthreads();
    epi_act(sm, acc, rowbase, colq, gid, tig);
    __syncthreads();

    // ---- layer 3 ----
    #pragma unroll
    for (int nt = 0; nt < 4; nt++) {
        int col = colq * 32 + nt * 8 + 2 * tig;
        float b0 = sb3[col], b1 = sb3[col + 1];
        #pragma unroll
        for (int q = 0; q < 4; q++) { acc[nt][q * 2] = b0; acc[nt][q * 2 + 1] = b1; }
    }
    do_gemm(smb + SM_W0, smb + SM_A, acc, rowbase, colq, lane);

    if (MODE == 0) {
        // masked values -> W1 region (dead), then per-token column sums
        __syncthreads();
        float* fA = (float*)(sm + SM_W1);
        #pragma unroll
        for (int nt = 0; nt < 4; nt++) {
            int col = colq * 32 + nt * 8 + 2 * tig;
            #pragma unroll
            for (int q = 0; q < 4; q++) {
                int row = rowbase + q * 8 + gid;
                float mk = smask[row];
                *(float2*)(fA + row * STG_LD + col) =
                    make_float2(mk * acc[nt][q * 2], mk * acc[nt][q * 2 + 1]);
            }
        }
        __syncthreads();
        int c = tid & 127, qtr = tid >> 7;
        int t0 = grow0 / KNB;
        for (int tok = t0 + qtr; KNB * tok < grow0 + 128; tok += 4) {
            int r0 = KNB * tok - grow0, r1 = r0 + KNB;
            if (r0 < 0) r0 = 0;
            if (r1 > 128) r1 = 128;
            float s = 0.f;
            for (int rr = r0; rr < r1; rr++) s += fA[rr * STG_LD + c];
            atomicAdd(&g_dh[(size_t)tok * H + c], s);
        }
    } else {
        // residual + per-row LN -> outE
        float sA[4], sB[4];
        #pragma unroll
        for (int q = 0; q < 4; q++) { sA[q] = 0.f; sB[q] = 0.f; }
        #pragma unroll
        for (int nt = 0; nt < 4; nt++) {
            int col = colq * 32 + nt * 8 + 2 * tig;
            #pragma unroll
            for (int q = 0; q < 4; q++) {
                int row = rowbase + q * 8 + gid;
                float2 res = *(const float2*)(hE + (size_t)(grow0 + row) * H + col);
                float x0 = acc[nt][q * 2]     + res.x;
                float x1 = acc[nt][q * 2 + 1] + res.y;
                acc[nt][q * 2] = x0; acc[nt][q * 2 + 1] = x1;
                sA[q] += x0 + x1;
                sB[q] += x0 * x0 + x1 * x1;
            }
        }
        #pragma unroll
        for (int q = 0; q < 4; q++) {
            sA[q] += __shfl_xor_sync(0xffffffffu, sA[q], 1);
            sA[q] += __shfl_xor_sync(0xffffffffu, sA[q], 2);
            sB[q] += __shfl_xor_sync(0xffffffffu, sB[q], 1);
            sB[q] += __shfl_xor_sync(0xffffffffu, sB[q], 2);
        }
        if (tig == 0) {
            #pragma unroll
            for (int q = 0; q < 4; q++) {
                int row = rowbase + q * 8 + gid;
                spar[colq * 128 + row]       = sA[q];
                spar[512 + colq * 128 + row] = sB[q];
            }
        }
        __syncthreads();
        float mV = 0.f, rV = 0.f;
        if (tid < 128) {
            float ss  = spar[tid] + spar[128 + tid] + spar[256 + tid] + spar[384 + tid];
            float ss2 = spar[512 + tid] + spar[640 + tid] + spar[768 + tid] + spar[896 + tid];
            mV = ss * (1.f / H);
            rV = rsqrtf(ss2 * (1.f / H) - mV * mV + 1e-5f);
        }
        __syncthreads();
        if (tid < 128) { spar[tid] = mV; spar[128 + tid] = rV; }
        __syncthreads();
        #pragma unroll
        for (int nt = 0; nt < 4; nt++) {
            int col = colq * 32 + nt * 8 + 2 * tig;
            float g0 = sg[col], g1 = sg[col + 1];
            float e0 = sbe[col], e1 = sbe[col + 1];
            #pragma unroll
            for (int q = 0; q < 4; q++) {
                int row = rowbase + q * 8 + gid;
                float m = spar[row], rs = spar[128 + row];
                float2 y;
                y.x = g0 * (acc[nt][q * 2]     - m) * rs + e0;
                y.y = g1 * (acc[nt][q * 2 + 1] - m) * rs + e1;
                *(float2*)(outE + (size_t)(grow0 + row) * H + col) = y;
            }
        }
    }
}

// ---------------- fp32 helpers for pre / ffn ----------------
template<int ROWS, int K4>
__device__ __forceinline__ void gemm_acc(float* acc, const float* A,
                                         const float* __restrict__ W,
                                         int n, int ldw) {
    const float4* A4 = reinterpret_cast<const float4*>(A);
    #pragma unroll 1
    for (int k4 = 0; k4 < K4; k4++) {
        const float* wp = W + (k4 * 4) * ldw + n;
        float w0 = wp[0], w1 = wp[ldw], w2 = wp[2 * ldw], w3 = wp[3 * ldw];
        #pragma unroll
        for (int rr = 0; rr < ROWS; rr++) {
            float4 a = A4[rr * K4 + k4];
            acc[rr] = fmaf(a.x, w0, acc[rr]);
            acc[rr] = fmaf(a.y, w1, acc[rr]);
            acc[rr] = fmaf(a.z, w2, acc[rr]);
            acc[rr] = fmaf(a.w, w3, acc[rr]);
        }
    }
}

__global__ void __launch_bounds__(128) k_pre(const float* __restrict__ hV,
                                             const float* __restrict__ W1,
                                             const float* __restrict__ b1,
                                             int ntok) {
    for (int i = blockIdx.x * 128 + threadIdx.x; i < ntok * H; i += gridDim.x * 128)
        g_dh[i] = 0.f;
    extern __shared__ float smf[];
    float* w1a = smf;
    float* w1c = smf + H * H;
    float* rows = smf + 2 * H * H;
    int tid = threadIdx.x;
    for (int i = tid; i < H * H; i += 128) {
        w1a[i] = W1[i];
        w1c[i] = W1[2 * H * H + i];
    }
    int t0 = blockIdx.x * 32;
    for (int i = tid; i < 32 * H; i += 128) rows[i] = hV[(size_t)t0 * H + i];
    __syncthreads();
    float bn = b1[tid];
    for (int rr = 0; rr < 32; rr++) {
        float a1 = bn, a3 = 0.f;
        const float4* rv = reinterpret_cast<const float4*>(rows + rr * H);
        #pragma unroll 8
        for (int k4 = 0; k4 < 32; k4++) {
            float4 v = rv[k4];
            int k = k4 * 4;
            a1 = fmaf(v.x, w1a[(k+0)*H+tid], a1); a1 = fmaf(v.y, w1a[(k+1)*H+tid], a1);
            a1 = fmaf(v.z, w1a[(k+2)*H+tid], a1); a1 = fmaf(v.w, w1a[(k+3)*H+tid], a1);
            a3 = fmaf(v.x, w1c[(k+0)*H+tid], a3); a3 = fmaf(v.y, w1c[(k+1)*H+tid], a3);
            a3 = fmaf(v.z, w1c[(k+2)*H+tid], a3); a3 = fmaf(v.w, w1c[(k+3)*H+tid], a3);
        }
        g_P1[(size_t)(t0+rr)*H+tid] = a1;
        g_P3[(size_t)(t0+rr)*H+tid] = a3;
    }
}

// FFN with fused LN1 head; 32 tokens/block, 512 threads (16 warps) for latency
__global__ void __launch_bounds__(512, 1) k_ffn(
    const float* __restrict__ hV,    const float* __restrict__ maskV,
    const float* __restrict__ g1,    const float* __restrict__ be1,
    const float* __restrict__ W_in,  const float* __restrict__ b_in,
    const float* __restrict__ W_out, const float* __restrict__ b_out,
    const float* __restrict__ g2,    const float* __restrict__ be2,
    const float* __restrict__ W11,   const float* __restrict__ b11,
    float* __restrict__ outV) {
    extern __shared__ float smf[];
    float* sX   = smf;               // 32*H
    float* sHid = smf + 32 * H;      // 32*512
    float* sMk  = sHid + 32 * 512;   // 32
    int tid = threadIdx.x;
    int t0 = blockIdx.x * 32;
    int col = tid & 127, qtr = tid >> 7;   // 4 row-quarters of 8 rows
    int warp = tid >> 5, lane = tid & 31;

    // LN1 fused: x = hV + g_dh/30, per-row LN -> sX (32 rows, 16 warps)
    for (int rr = warp; rr < 32; rr += 16) {
        size_t base = (size_t)(t0 + rr) * H;
        float v[4];
        #pragma unroll
        for (int j = 0; j < 4; j++) {
            int n = lane + 32 * j;
            v[j] = hV[base + n] + g_dh[base + n] * (1.f / 30.f);
        }
        float s = v[0]+v[1]+v[2]+v[3];
        float s2 = v[0]*v[0]+v[1]*v[1]+v[2]*v[2]+v[3]*v[3];
        #pragma unroll
        for (int o = 16; o; o >>= 1) {
            s  += __shfl_xor_sync(0xffffffffu, s,  o);
            s2 += __shfl_xor_sync(0xffffffffu, s2, o);
        }
        float m = s * (1.f/H);
        float rs = rsqrtf(s2 * (1.f/H) - m*m + 1e-5f);
        #pragma unroll
        for (int j = 0; j < 4; j++) {
            int n = lane + 32 * j;
            sX[rr * H + n] = g1[n] * (v[j] - m) * rs + be1[n];
        }
    }
    if (tid < 32) sMk[tid] = maskV[t0 + tid];
    __syncthreads();

    // hidden layer: 512 cols, ONE col per thread, 32 rows each
    {
        float acc[32];
        float bi = b_in[tid];
        #pragma unroll
        for (int rr = 0; rr < 32; rr++) acc[rr] = bi;
        gemm_acc<32, 32>(acc, sX, W_in, tid, 512);
        #pragma unroll
        for (int rr = 0; rr < 32; rr++) sHid[rr * 512 + tid] = gelu_f(acc[rr]);
    }
    __syncthreads();

    // output layer + residual: 8 rows per quarter
    {
        float acc[8];
        float bo = b_out[col];
        #pragma unroll
        for (int rr = 0; rr < 8; rr++) acc[rr] = bo;
        gemm_acc<8, 128>(acc, sHid + qtr * 8 * 512, W_out, col, H);
        #pragma unroll
        for (int rr = 0; rr < 8; rr++)
            acc[rr] += sX[(qtr * 8 + rr) * H + col];
        __syncthreads();
        #pragma unroll
        for (int rr = 0; rr < 8; rr++)
            sHid[(qtr * 8 + rr) * H + col] = acc[rr];
    }
    __syncthreads();

    // per-row LN2 + mask (16 warps, 2 rows each)
    for (int rr = warp; rr < 32; rr += 16) {
        const float* row = sHid + rr * H;
        float v[4] = { row[lane], row[lane+32], row[lane+64], row[lane+96] };
        float s = v[0]+v[1]+v[2]+v[3];
        float s2 = v[0]*v[0]+v[1]*v[1]+v[2]*v[2]+v[3]*v[3];
        #pragma unroll
        for (int o = 16; o; o >>= 1) {
            s  += __shfl_xor_sync(0xffffffffu, s,  o);
            s2 += __shfl_xor_sync(0xffffffffu, s2, o);
        }
        float m = s * (1.f/H);
        float rs = rsqrtf(s2 * (1.f/H) - m*m + 1e-5f);
        float mk = sMk[rr];
        #pragma unroll
        for (int j = 0; j < 4; j++) {
            int n = lane + 32*j;
            float y = mk * (g2[n]*(v[j]-m)*rs + be2[n]);
            outV[(size_t)(t0+rr)*H + n] = y;
            sX[rr*H + n] = y;
        }
    }
    __syncthreads();

    // P11 / P13 precompute: 8 rows per quarter
    {
        float acc2[8];
        float bb = b11[col];
        #pragma unroll
        for (int rr = 0; rr < 8; rr++) acc2[rr] = bb;
        gemm_acc<8, 32>(acc2, sX + qtr * 8 * H, W11, col, H);
        #pragma unroll
        for (int rr = 0; rr < 8; rr++)
            g_P11[(size_t)(t0 + qtr * 8 + rr) * H + col] = acc2[rr];
        #pragma unroll
        for (int rr = 0; rr < 8; rr++) acc2[rr] = 0.f;
        gemm_acc<8, 32>(acc2, sX + qtr * 8 * H, W11 + 2 * H * H, col, H);
        #pragma unroll
        for (int rr = 0; rr < 8; rr++)
            g_P13[(size_t)(t0 + qtr * 8 + rr) * H + col] = acc2[rr];
    }
}

// ---------------------------------------------------------------------------
extern "C" void kernel_launch(void* const* d_in, const int* in_sizes, int n_in,
                              void* d_out, int out_size) {
    const float* hV    = (const float*)d_in[0];
    const float* hE    = (const float*)d_in[1];
    const int*   Eidx  = (const int*)  d_in[2];
    const float* maskV = (const float*)d_in[3];
    const float* matt  = (const float*)d_in[4];
    const float* W1    = (const float*)d_in[5];
    const float* b1    = (const float*)d_in[6];
    const float* W2    = (const float*)d_in[7];
    const float* b2    = (const float*)d_in[8];
    const float* W3    = (const float*)d_in[9];
    const float* b3    = (const float*)d_in[10];
    const float* W11   = (const float*)d_in[11];
    const float* b11   = (const float*)d_in[12];
    const float* W12   = (const float*)d_in[13];
    const float* b12   = (const float*)d_in[14];
    const float* W13   = (const float*)d_in[15];
    const float* b13   = (const float*)d_in[16];
    const float* g1    = (const float*)d_in[17];
    const float* be1   = (const float*)d_in[18];
    const float* g2    = (const float*)d_in[19];
    const float* be2   = (const float*)d_in[20];
    const float* g3    = (const float*)d_in[21];
    const float* be3   = (const float*)d_in[22];
    const float* W_in  = (const float*)d_in[23];
    const float* b_in  = (const float*)d_in[24];
    const float* W_out = (const float*)d_in[25];
    const float* b_out = (const float*)d_in[26];

    int ntok = in_sizes[3];

    size_t smemP = (size_t)(2 * H * H + 32 * H) * sizeof(float);
    size_t smemB = (size_t)(32 * H + 32 * 512 + 64) * sizeof(float);

    cudaFuncSetAttribute(k_pre,    cudaFuncAttributeMaxDynamicSharedMemorySize, (int)smemP);
    cudaFuncSetAttribute(k_ffn,    cudaFuncAttributeMaxDynamicSharedMemorySize, (int)smemB);
    cudaFuncSetAttribute(k_mlp<0>, cudaFuncAttributeMaxDynamicSharedMemorySize, SMEM_MLP);
    cudaFuncSetAttribute(k_mlp<1>, cudaFuncAttributeMaxDynamicSharedMemorySize, SMEM_MLP);

    float* outV = (float*)d_out;
    float* outE = outV + (size_t)ntok * H;
    int ntile = ntok * KNB / 128;

    k_wprep<<< 6 * 16384 / 256, 256 >>>(W1 + H * H, W2, W3, W11 + H * H, W12, W13);
    k_pre  <<< ntok / 32, 128, smemP >>>(hV, W1, b1, ntok);
    k_mlp<0><<< ntile, 512, SMEM_MLP >>>(hE, Eidx, b2, b3, g1, be1, matt, outE);
    k_ffn  <<< ntok / 32, 512, smemB >>>(hV, maskV, g1, be1, W_in, b_in, W_out, b_out,
                                         g2, be2, W11, b11, outV);
    k_mlp<1><<< ntile, 512, SMEM_MLP >>>(hE, Eidx, b12, b13, g3, be3, matt, outE);
}

// round 16
// speedup vs baseline: 1.0070x; 1.0070x over previous
#include <cuda_runtime.h>
#include <cuda_fp16.h>
#include <math.h>
#include <cstdint>

#define H    128
#define KNB  48
#define LSEQ 2048
#define NTOK_MAX 4096

// ---------------- device scratch ----------------
__device__ float g_P1 [NTOK_MAX * H];
__device__ float g_P3 [NTOK_MAX * H];
__device__ float g_P11[NTOK_MAX * H];
__device__ float g_P13[NTOK_MAX * H];
__device__ float g_dh [NTOK_MAX * H];
// 6 weight mats, transposed [n][k], fp16 hi then fp16 lo (each 16384)
__device__ __half g_W[6 * 32768];

__device__ __forceinline__ float gelu_f(float x) {
    return 0.5f * x * (1.0f + erff(x * 0.70710678118654752f));
}

__device__ __forceinline__ uint32_t smem_u32(const void* p) {
    uint32_t a;
    asm("{ .reg .u64 t; cvta.to.shared.u64 t, %1; cvt.u32.u64 %0, t; }" : "=r"(a) : "l"(p));
    return a;
}

__device__ __forceinline__ void mma16816(float* c, const uint32_t* a,
                                         uint32_t b0, uint32_t b1) {
    asm volatile(
        "mma.sync.aligned.m16n8k16.row.col.f32.f16.f16.f32 "
        "{%0,%1,%2,%3}, {%4,%5,%6,%7}, {%8,%9}, {%0,%1,%2,%3};"
        : "+f"(c[0]), "+f"(c[1]), "+f"(c[2]), "+f"(c[3])
        : "r"(a[0]), "r"(a[1]), "r"(a[2]), "r"(a[3]), "r"(b0), "r"(b1));
}

#define LDSM4(r0, r1, r2, r3, addr) \
    asm volatile("ldmatrix.sync.aligned.m8n8.x4.shared.b16 {%0,%1,%2,%3}, [%4];" \
                 : "=r"(r0), "=r"(r1), "=r"(r2), "=r"(r3) : "r"(addr))

#define CP_COMMIT() asm volatile("cp.async.commit_group;" ::: "memory")
#define CP_WAIT0()  asm volatile("cp.async.wait_group 0;" ::: "memory")

// ---------------- smem layout (bytes) ----------------
#define LDA    136
#define STG_LD 130
#define SLAB  34816          // 128*136*2
#define SM_W0   0            // weight buf 0: hi slab + lo slab (69632)
#define SM_W1   69632        // weight buf 1 (also MODE0 staging late)
#define SM_A    139264       // activations: SINGLE fp16 slab (34816)
#define SM_NBR  174080       // 128 int
#define SM_MASK 174592       // 128 f
#define SM_B2   175104
#define SM_B3   175616
#define SM_G    176128
#define SM_BE   176640
#define SM_PAR  177152       // 1024 f = 4096
#define SMEM_MLP 181248

// ---------------- weight prep: transpose + fp16 hi/lo split ----------------
__global__ void k_wprep(const float* W1b, const float* W2, const float* W3,
                        const float* W11b, const float* W12, const float* W13) {
    int id = blockIdx.x * 256 + threadIdx.x;    // 6*16384
    int m = id >> 14, e = id & 16383;
    int n = e >> 7, k = e & 127;
    const float* srcs[6] = {W1b, W2, W3, W11b, W12, W13};
    float v = srcs[m][k * H + n];
    __half h = __float2half_rn(v);
    g_W[m * 32768 + e]         = h;
    g_W[m * 32768 + 16384 + e] = __float2half_rn(v - __half2float(h));
}

// async weight load (512 threads): 4096 x 16B
__device__ __forceinline__ void load_w_async(uint32_t smDst, int tid, int mat) {
    const char* src = (const char*)(g_W + (size_t)mat * 32768);
    #pragma unroll
    for (int it = 0; it < 8; it++) {
        int id = tid + it * 512;
        int hl = id >> 11, j = id & 2047;
        int n = j >> 4, kc = (j & 15) << 3;
        uint32_t dst = smDst + hl * SLAB + (uint32_t)((n * LDA + kc) * 2);
        asm volatile("cp.async.cg.shared.global [%0], [%1], 16;"
                     :: "r"(dst), "l"(src + (size_t)id * 16));
    }
}

// 2-pass GEMM (A fp16, W hi+lo): acc[4][8] += A(128x128) x W^T (warp: 32x32)
__device__ __forceinline__ void do_gemm(uint32_t wBase, uint32_t aBase, float acc[4][8],
                                        int rowbase, int colq, int lane) {
    int arow = rowbase + (lane & 15);
    int acol = (lane >> 4) << 3;
    uint32_t aOff = aBase + (uint32_t)((arow * LDA + acol) * 2);
    int nrow = colq * 32 + (lane & 7) + ((lane >> 4) << 3);
    int bcol = ((lane >> 3) & 1) << 3;
    uint32_t bOff = wBase + (uint32_t)((nrow * LDA + bcol) * 2);
    #pragma unroll 1
    for (int pass = 0; pass < 2; pass++) {
        uint32_t bB = bOff + ((pass == 1) ? SLAB : 0);
        #pragma unroll 1
        for (int ks = 0; ks < 8; ks++) {
            uint32_t a0[4], a1[4];
            LDSM4(a0[0], a0[1], a0[2], a0[3], aOff + ks * 32);
            LDSM4(a1[0], a1[1], a1[2], a1[3], aOff + 16 * LDA * 2 + ks * 32);
            #pragma unroll
            for (int ntp = 0; ntp < 2; ntp++) {
                uint32_t b0, b1, b2, b3;
                LDSM4(b0, b1, b2, b3, bB + ntp * 16 * LDA * 2 + ks * 32);
                mma16816(&acc[2 * ntp][0],     a0, b0, b1);
                mma16816(&acc[2 * ntp][4],     a1, b0, b1);
                mma16816(&acc[2 * ntp + 1][0], a0, b2, b3);
                mma16816(&acc[2 * ntp + 1][4], a1, b2, b3);
            }
        }
    }
}

// GELU(acc) -> A slab (fp16), for next layer's input
__device__ __forceinline__ void epi_act(char* sm, float acc[4][8],
                                        int rowbase, int colq, int gid, int tig) {
    #pragma unroll
    for (int nt = 0; nt < 4; nt++) {
        int col = colq * 32 + nt * 8 + 2 * tig;
        #pragma unroll
        for (int q = 0; q < 4; q++) {
            int row = rowbase + q * 8 + gid;
            __half2 h = __floats2half2_rn(gelu_f(acc[nt][q * 2]),
                                          gelu_f(acc[nt][q * 2 + 1]));
            *(uint32_t*)(sm + SM_A + (row * LDA + col) * 2) =
                *reinterpret_cast<uint32_t*>(&h);
        }
    }
}

// ---------------- fused 3-layer MLP over one 128-row tile (512 thr) ----------
// MODE 0: node messages -> masked per-token sums into g_dh (atomic)
// MODE 1: edge update -> +hE residual, row LN, write outE
template <int MODE>
__global__ void __launch_bounds__(512, 1) k_mlp(
    const float* __restrict__ hE, const int* __restrict__ Eidx,
    const float* __restrict__ bias2, const float* __restrict__ bias3,
    const float* __restrict__ lng, const float* __restrict__ lnb,
    const float* __restrict__ mattend, float* __restrict__ outE) {
    extern __shared__ char sm[];
    int*   snbr  = (int*)(sm + SM_NBR);
    float* smask = (float*)(sm + SM_MASK);
    float* sb2   = (float*)(sm + SM_B2);
    float* sb3   = (float*)(sm + SM_B3);
    float* sg    = (float*)(sm + SM_G);
    float* sbe   = (float*)(sm + SM_BE);
    float* spar  = (float*)(sm + SM_PAR);

    int tid = threadIdx.x, wid = tid >> 5, lane = tid & 31;
    int gid = lane >> 2, tig = lane & 3;
    int rowbase = (wid & 3) * 32;
    int colq = wid >> 2;
    int grow0 = blockIdx.x * 128;
    uint32_t smb = smem_u32(sm);

    load_w_async(smb + SM_W0, tid, MODE * 3 + 0);
    CP_COMMIT();

    if (tid < 128) {
        int gr = grow0 + tid;
        int t = gr / KNB;
        snbr[tid] = (t / LSEQ) * LSEQ + Eidx[gr];
        smask[tid] = (MODE == 0) ? mattend[gr] : 0.f;
        sb2[tid] = bias2[tid]; sb3[tid] = bias3[tid];
        sg[tid] = lng[tid];    sbe[tid] = lnb[tid];
    }

    // A <- fp16(hE tile)
    const float4* hE4 = reinterpret_cast<const float4*>(hE + (size_t)grow0 * H);
    #pragma unroll
    for (int it = 0; it < 8; it++) {
        int id = tid + it * 512;
        int rr = id >> 5, c4 = id & 31;
        float4 v = hE4[rr * 32 + c4];
        __half2 h01 = __floats2half2_rn(v.x, v.y);
        __half2 h23 = __floats2half2_rn(v.z, v.w);
        *(uint2*)(sm + SM_A + (rr * LDA + c4 * 4) * 2) =
            make_uint2(*reinterpret_cast<uint32_t*>(&h01),
                       *reinterpret_cast<uint32_t*>(&h23));
    }
    CP_WAIT0();
    __syncthreads();

    float acc[4][8];

    // ---- layer 1: acc init = P_center + P_nbr (exact fp32, from global) ----
    {
        const float* Padd = (MODE == 0) ? g_P1 : g_P11;
        const float* Pnbr = (MODE == 0) ? g_P3 : g_P13;
        int tokv[4], nbv[4];
        #pragma unroll
        for (int q = 0; q < 4; q++) {
            int row = rowbase + q * 8 + gid;
            tokv[q] = (grow0 + row) / KNB;
            nbv[q] = snbr[row];
        }
        #pragma unroll
        for (int nt = 0; nt < 4; nt++) {
            int col = colq * 32 + nt * 8 + 2 * tig;
            #pragma unroll
            for (int q = 0; q < 4; q++) {
                float2 a = *(const float2*)(Padd + (size_t)tokv[q] * H + col);
                float2 b = *(const float2*)(Pnbr + (size_t)nbv[q] * H + col);
                acc[nt][q * 2] = a.x + b.x; acc[nt][q * 2 + 1] = a.y + b.y;
            }
        }
    }
    load_w_async(smb + SM_W1, tid, MODE * 3 + 1);
    CP_COMMIT();
    do_gemm(smb + SM_W0, smb + SM_A, acc, rowbase, colq, lane);
    CP_WAIT0();
    __syncthreads();
    epi_act(sm, acc, rowbase, colq, gid, tig);
    __syncthreads();

    // ---- layer 2 ----
    #pragma unroll
    for (int nt = 0; nt < 4; nt++) {
        int col = colq * 32 + nt * 8 + 2 * tig;
        float b0 = sb2[col], b1 = sb2[col + 1];
        #pragma unroll
        for (int q = 0; q < 4; q++) { acc[nt][q * 2] = b0; acc[nt][q * 2 + 1] = b1; }
    }
    load_w_async(smb + SM_W0, tid, MODE * 3 + 2);
    CP_COMMIT();
    do_gemm(smb + SM_W1, smb + SM_A, acc, rowbase, colq, lane);
    CP_WAIT0();
    __syncthreads();
    epi_act(sm, acc, rowbase, colq, gid, tig);
    __syncthreads();

    // ---- layer 3 ----
    #pragma unroll
    for (int nt = 0; nt < 4; nt++) {
        int col = colq * 32 + nt * 8 + 2 * tig;
        float b0 = sb3[col], b1 = sb3[col + 1];
        #pragma unroll
        for (int q = 0; q < 4; q++) { acc[nt][q * 2] = b0; acc[nt][q * 2 + 1] = b1; }
    }
    do_gemm(smb + SM_W0, smb + SM_A, acc, rowbase, colq, lane);

    if (MODE == 0) {
        // masked values -> W1 region (dead), then per-token column sums
        __syncthreads();
        float* fA = (float*)(sm + SM_W1);
        #pragma unroll
        for (int nt = 0; nt < 4; nt++) {
            int col = colq * 32 + nt * 8 + 2 * tig;
            #pragma unroll
            for (int q = 0; q < 4; q++) {
                int row = rowbase + q * 8 + gid;
                float mk = smask[row];
                *(float2*)(fA + row * STG_LD + col) =
                    make_float2(mk * acc[nt][q * 2], mk * acc[nt][q * 2 + 1]);
            }
        }
        __syncthreads();
        int c = tid & 127, qtr = tid >> 7;
        int t0 = grow0 / KNB;
        for (int tok = t0 + qtr; KNB * tok < grow0 + 128; tok += 4) {
            int r0 = KNB * tok - grow0, r1 = r0 + KNB;
            if (r0 < 0) r0 = 0;
            if (r1 > 128) r1 = 128;
            float s = 0.f;
            for (int rr = r0; rr < r1; rr++) s += fA[rr * STG_LD + c];
            atomicAdd(&g_dh[(size_t)tok * H + c], s);
        }
    } else {
        // residual + per-row LN -> outE
        float sA[4], sB[4];
        #pragma unroll
        for (int q = 0; q < 4; q++) { sA[q] = 0.f; sB[q] = 0.f; }
        #pragma unroll
        for (int nt = 0; nt < 4; nt++) {
            int col = colq * 32 + nt * 8 + 2 * tig;
            #pragma unroll
            for (int q = 0; q < 4; q++) {
                int row = rowbase + q * 8 + gid;
                float2 res = *(const float2*)(hE + (size_t)(grow0 + row) * H + col);
                float x0 = acc[nt][q * 2]     + res.x;
                float x1 = acc[nt][q * 2 + 1] + res.y;
                acc[nt][q * 2] = x0; acc[nt][q * 2 + 1] = x1;
                sA[q] += x0 + x1;
                sB[q] += x0 * x0 + x1 * x1;
            }
        }
        #pragma unroll
        for (int q = 0; q < 4; q++) {
            sA[q] += __shfl_xor_sync(0xffffffffu, sA[q], 1);
            sA[q] += __shfl_xor_sync(0xffffffffu, sA[q], 2);
            sB[q] += __shfl_xor_sync(0xffffffffu, sB[q], 1);
            sB[q] += __shfl_xor_sync(0xffffffffu, sB[q], 2);
        }
        if (tig == 0) {
            #pragma unroll
            for (int q = 0; q < 4; q++) {
                int row = rowbase + q * 8 + gid;
                spar[colq * 128 + row]       = sA[q];
                spar[512 + colq * 128 + row] = sB[q];
            }
        }
        __syncthreads();
        float mV = 0.f, rV = 0.f;
        if (tid < 128) {
            float ss  = spar[tid] + spar[128 + tid] + spar[256 + tid] + spar[384 + tid];
            float ss2 = spar[512 + tid] + spar[640 + tid] + spar[768 + tid] + spar[896 + tid];
            mV = ss * (1.f / H);
            rV = rsqrtf(ss2 * (1.f / H) - mV * mV + 1e-5f);
        }
        __syncthreads();
        if (tid < 128) { spar[tid] = mV; spar[128 + tid] = rV; }
        __syncthreads();
        #pragma unroll
        for (int nt = 0; nt < 4; nt++) {
            int col = colq * 32 + nt * 8 + 2 * tig;
            float g0 = sg[col], g1 = sg[col + 1];
            float e0 = sbe[col], e1 = sbe[col + 1];
            #pragma unroll
            for (int q = 0; q < 4; q++) {
                int row = rowbase + q * 8 + gid;
                float m = spar[row], rs = spar[128 + row];
                float2 y;
                y.x = g0 * (acc[nt][q * 2]     - m) * rs + e0;
                y.y = g1 * (acc[nt][q * 2 + 1] - m) * rs + e1;
                *(float2*)(outE + (size_t)(grow0 + row) * H + col) = y;
            }
        }
    }
}

// ---------------- fp32 helpers for pre / ffn ----------------
template<int ROWS, int K4>
__device__ __forceinline__ void gemm_acc(float* acc, const float* A,
                                         const float* __restrict__ W,
                                         int n, int ldw) {
    const float4* A4 = reinterpret_cast<const float4*>(A);
    #pragma unroll 1
    for (int k4 = 0; k4 < K4; k4++) {
        const float* wp = W + (k4 * 4) * ldw + n;
        float w0 = wp[0], w1 = wp[ldw], w2 = wp[2 * ldw], w3 = wp[3 * ldw];
        #pragma unroll
        for (int rr = 0; rr < ROWS; rr++) {
            float4 a = A4[rr * K4 + k4];
            acc[rr] = fmaf(a.x, w0, acc[rr]);
            acc[rr] = fmaf(a.y, w1, acc[rr]);
            acc[rr] = fmaf(a.z, w2, acc[rr]);
            acc[rr] = fmaf(a.w, w3, acc[rr]);
        }
    }
}

__global__ void __launch_bounds__(128) k_pre(const float* __restrict__ hV,
                                             const float* __restrict__ W1,
                                             const float* __restrict__ b1,
                                             int ntok) {
    for (int i = blockIdx.x * 128 + threadIdx.x; i < ntok * H; i += gridDim.x * 128)
        g_dh[i] = 0.f;
    extern __shared__ float smf[];
    float* w1a = smf;
    float* w1c = smf + H * H;
    float* rows = smf + 2 * H * H;
    int tid = threadIdx.x;
    for (int i = tid; i < H * H; i += 128) {
        w1a[i] = W1[i];
        w1c[i] = W1[2 * H * H + i];
    }
    int t0 = blockIdx.x * 32;
    for (int i = tid; i < 32 * H; i += 128) rows[i] = hV[(size_t)t0 * H + i];
    __syncthreads();
    float bn = b1[tid];
    for (int rr = 0; rr < 32; rr++) {
        float a1 = bn, a3 = 0.f;
        const float4* rv = reinterpret_cast<const float4*>(rows + rr * H);
        #pragma unroll 8
        for (int k4 = 0; k4 < 32; k4++) {
            float4 v = rv[k4];
            int k = k4 * 4;
            a1 = fmaf(v.x, w1a[(k+0)*H+tid], a1); a1 = fmaf(v.y, w1a[(k+1)*H+tid], a1);
            a1 = fmaf(v.z, w1a[(k+2)*H+tid], a1); a1 = fmaf(v.w, w1a[(k+3)*H+tid], a1);
            a3 = fmaf(v.x, w1c[(k+0)*H+tid], a3); a3 = fmaf(v.y, w1c[(k+1)*H+tid], a3);
            a3 = fmaf(v.z, w1c[(k+2)*H+tid], a3); a3 = fmaf(v.w, w1c[(k+3)*H+tid], a3);
        }
        g_P1[(size_t)(t0+rr)*H+tid] = a1;
        g_P3[(size_t)(t0+rr)*H+tid] = a3;
    }
}

// FFN with fused LN1 head; 32 tokens/block, 512 threads (16 warps) for latency
__global__ void __launch_bounds__(512, 1) k_ffn(
    const float* __restrict__ hV,    const float* __restrict__ maskV,
    const float* __restrict__ g1,    const float* __restrict__ be1,
    const float* __restrict__ W_in,  const float* __restrict__ b_in,
    const float* __restrict__ W_out, const float* __restrict__ b_out,
    const float* __restrict__ g2,    const float* __restrict__ be2,
    const float* __restrict__ W11,   const float* __restrict__ b11,
    float* __restrict__ outV) {
    extern __shared__ float smf[];
    float* sX   = smf;               // 32*H
    float* sHid = smf + 32 * H;      // 32*512
    float* sMk  = sHid + 32 * 512;   // 32
    int tid = threadIdx.x;
    int t0 = blockIdx.x * 32;
    int col = tid & 127, qtr = tid >> 7;   // 4 row-quarters of 8 rows
    int warp = tid >> 5, lane = tid & 31;

    // LN1 fused: x = hV + g_dh/30, per-row LN -> sX (32 rows, 16 warps)
    for (int rr = warp; rr < 32; rr += 16) {
        size_t base = (size_t)(t0 + rr) * H;
        float v[4];
        #pragma unroll
        for (int j = 0; j < 4; j++) {
            int n = lane + 32 * j;
            v[j] = hV[base + n] + g_dh[base + n] * (1.f / 30.f);
        }
        float s = v[0]+v[1]+v[2]+v[3];
        float s2 = v[0]*v[0]+v[1]*v[1]+v[2]*v[2]+v[3]*v[3];
        #pragma unroll
        for (int o = 16; o; o >>= 1) {
            s  += __shfl_xor_sync(0xffffffffu, s,  o);
            s2 += __shfl_xor_sync(0xffffffffu, s2, o);
        }
        float m = s * (1.f/H);
        float rs = rsqrtf(s2 * (1.f/H) - m*m + 1e-5f);
        #pragma unroll
        for (int j = 0; j < 4; j++) {
            int n = lane + 32 * j;
            sX[rr * H + n] = g1[n] * (v[j] - m) * rs + be1[n];
        }
    }
    if (tid < 32) sMk[tid] = maskV[t0 + tid];
    __syncthreads();

    // hidden layer: 512 cols, ONE col per thread, 32 rows each
    {
        float acc[32];
        float bi = b_in[tid];
        #pragma unroll
        for (int rr = 0; rr < 32; rr++) acc[rr] = bi;
        gemm_acc<32, 32>(acc, sX, W_in, tid, 512);
        #pragma unroll
        for (int rr = 0; rr < 32; rr++) sHid[rr * 512 + tid] = gelu_f(acc[rr]);
    }
    __syncthreads();

    // output layer + residual: 8 rows per quarter
    {
        float acc[8];
        float bo = b_out[col];
        #pragma unroll
        for (int rr = 0; rr < 8; rr++) acc[rr] = bo;
        gemm_acc<8, 128>(acc, sHid + qtr * 8 * 512, W_out, col, H);
        #pragma unroll
        for (int rr = 0; rr < 8; rr++)
            acc[rr] += sX[(qtr * 8 + rr) * H + col];
        __syncthreads();
        #pragma unroll
        for (int rr = 0; rr < 8; rr++)
            sHid[(qtr * 8 + rr) * H + col] = acc[rr];
    }
    __syncthreads();

    // per-row LN2 + mask (16 warps, 2 rows each)
    for (int rr = warp; rr < 32; rr += 16) {
        const float* row = sHid + rr * H;
        float v[4] = { row[lane], row[lane+32], row[lane+64], row[lane+96] };
        float s = v[0]+v[1]+v[2]+v[3];
        float s2 = v[0]*v[0]+v[1]*v[1]+v[2]*v[2]+v[3]*v[3];
        #pragma unroll
        for (int o = 16; o; o >>= 1) {
            s  += __shfl_xor_sync(0xffffffffu, s,  o);
            s2 += __shfl_xor_sync(0xffffffffu, s2, o);
        }
        float m = s * (1.f/H);
        float rs = rsqrtf(s2 * (1.f/H) - m*m + 1e-5f);
        float mk = sMk[rr];
        #pragma unroll
        for (int j = 0; j < 4; j++) {
            int n = lane + 32*j;
            float y = mk * (g2[n]*(v[j]-m)*rs + be2[n]);
            outV[(size_t)(t0+rr)*H + n] = y;
            sX[rr*H + n] = y;
        }
    }
    __syncthreads();

    // P11 / P13 precompute: 8 rows per quarter
    {
        float acc2[8];
        float bb = b11[col];
        #pragma unroll
        for (int rr = 0; rr < 8; rr++) acc2[rr] = bb;
        gemm_acc<8, 32>(acc2, sX + qtr * 8 * H, W11, col, H);
        #pragma unroll
        for (int rr = 0; rr < 8; rr++)
            g_P11[(size_t)(t0 + qtr * 8 + rr) * H + col] = acc2[rr];
        #pragma unroll
        for (int rr = 0; rr < 8; rr++) acc2[rr] = 0.f;
        gemm_acc<8, 32>(acc2, sX + qtr * 8 * H, W11 + 2 * H * H, col, H);
        #pragma unroll
        for (int rr = 0; rr < 8; rr++)
            g_P13[(size_t)(t0 + qtr * 8 + rr) * H + col] = acc2[rr];
    }
}

// ---------------------------------------------------------------------------
extern "C" void kernel_launch(void* const* d_in, const int* in_sizes, int n_in,
                              void* d_out, int out_size) {
    const float* hV    = (const float*)d_in[0];
    const float* hE    = (const float*)d_in[1];
    const int*   Eidx  = (const int*)  d_in[2];
    const float* maskV = (const float*)d_in[3];
    const float* matt  = (const float*)d_in[4];
    const float* W1    = (const float*)d_in[5];
    const float* b1    = (const float*)d_in[6];
    const float* W2    = (const float*)d_in[7];
    const float* b2    = (const float*)d_in[8];
    const float* W3    = (const float*)d_in[9];
    const float* b3    = (const float*)d_in[10];
    const float* W11   = (const float*)d_in[11];
    const float* b11   = (const float*)d_in[12];
    const float* W12   = (const float*)d_in[13];
    const float* b12   = (const float*)d_in[14];
    const float* W13   = (const float*)d_in[15];
    const float* b13   = (const float*)d_in[16];
    const float* g1    = (const float*)d_in[17];
    const float* be1   = (const float*)d_in[18];
    const float* g2    = (const float*)d_in[19];
    const float* be2   = (const float*)d_in[20];
    const float* g3    = (const float*)d_in[21];
    const float* be3   = (const float*)d_in[22];
    const float* W_in  = (const float*)d_in[23];
    const float* b_in  = (const float*)d_in[24];
    const float* W_out = (const float*)d_in[25];
    const float* b_out = (const float*)d_in[26];

    int ntok = in_sizes[3];

    size_t smemP = (size_t)(2 * H * H + 32 * H) * sizeof(float);
    size_t smemB = (size_t)(32 * H + 32 * 512 + 64) * sizeof(float);

    cudaFuncSetAttribute(k_pre,    cudaFuncAttributeMaxDynamicSharedMemorySize, (int)smemP);
    cudaFuncSetAttribute(k_ffn,    cudaFuncAttributeMaxDynamicSharedMemorySize, (int)smemB);
    cudaFuncSetAttribute(k_mlp<0>, cudaFuncAttributeMaxDynamicSharedMemorySize, SMEM_MLP);
    cudaFuncSetAttribute(k_mlp<1>, cudaFuncAttributeMaxDynamicSharedMemorySize, SMEM_MLP);

    float* outV = (float*)d_out;
    float* outE = outV + (size_t)ntok * H;
    int ntile = ntok * KNB / 128;

    k_wprep<<< 6 * 16384 / 256, 256 >>>(W1 + H * H, W2, W3, W11 + H * H, W12, W13);
    k_pre  <<< ntok / 32, 128, smemP >>>(hV, W1, b1, ntok);
    k_mlp<0><<< ntile, 512, SMEM_MLP >>>(hE, Eidx, b2, b3, g1, be1, matt, outE);
    k_ffn  <<< ntok / 32, 512, smemB >>>(hV, maskV, g1, be1, W_in, b_in, W_out, b_out,
                                         g2, be2, W11, b11, outV);
    k_mlp<1><<< ntile, 512, SMEM_MLP >>>(hE, Eidx, b12, b13, g3, be3, matt, outE);
}

// round 17
// speedup vs baseline: 1.0135x; 1.0064x over previous
#include <cuda_runtime.h>
#include <cuda_fp16.h>
#include <math.h>
#include <cstdint>

#define H    128
#define KNB  48
#define LSEQ 2048
#define NTOK_MAX 4096

// ---------------- device scratch ----------------
__device__ float g_P1 [NTOK_MAX * H];
__device__ float g_P3 [NTOK_MAX * H];
__device__ float g_P11[NTOK_MAX * H];
__device__ float g_P13[NTOK_MAX * H];
__device__ float g_dh [NTOK_MAX * H];
// 6 weight mats, transposed [n][k], fp16 hi then fp16 lo (each 16384)
__device__ __half g_W[6 * 32768];

__device__ __forceinline__ float gelu_f(float x) {
    return 0.5f * x * (1.0f + erff(x * 0.70710678118654752f));
}

__device__ __forceinline__ uint32_t smem_u32(const void* p) {
    uint32_t a;
    asm("{ .reg .u64 t; cvta.to.shared.u64 t, %1; cvt.u32.u64 %0, t; }" : "=r"(a) : "l"(p));
    return a;
}

__device__ __forceinline__ void mma16816(float* c, const uint32_t* a,
                                         uint32_t b0, uint32_t b1) {
    asm volatile(
        "mma.sync.aligned.m16n8k16.row.col.f32.f16.f16.f32 "
        "{%0,%1,%2,%3}, {%4,%5,%6,%7}, {%8,%9}, {%0,%1,%2,%3};"
        : "+f"(c[0]), "+f"(c[1]), "+f"(c[2]), "+f"(c[3])
        : "r"(a[0]), "r"(a[1]), "r"(a[2]), "r"(a[3]), "r"(b0), "r"(b1));
}

#define LDSM4(r0, r1, r2, r3, addr) \
    asm volatile("ldmatrix.sync.aligned.m8n8.x4.shared.b16 {%0,%1,%2,%3}, [%4];" \
                 : "=r"(r0), "=r"(r1), "=r"(r2), "=r"(r3) : "r"(addr))

#define CP_COMMIT() asm volatile("cp.async.commit_group;" ::: "memory")
#define CP_WAIT0()  asm volatile("cp.async.wait_group 0;" ::: "memory")

// ---------------- smem layout (bytes) ----------------
#define LDA    136
#define STG_LD 130
#define SLAB  34816          // 128*136*2
#define SM_W0   0            // weight buf 0: hi slab + lo slab (69632)
#define SM_W1   69632        // weight buf 1 (also MODE0 staging late)
#define SM_A    139264       // activations: SINGLE fp16 slab (34816)
#define SM_NBR  174080       // 128 int
#define SM_MASK 174592       // 128 f
#define SM_B2   175104
#define SM_B3   175616
#define SM_G    176128
#define SM_BE   176640
#define SM_PAR  177152       // 1024 f = 4096
#define SMEM_MLP 181248

// ---------------- weight prep: transpose + fp16 hi/lo split ----------------
__global__ void k_wprep(const float* W1b, const float* W2, const float* W3,
                        const float* W11b, const float* W12, const float* W13) {
    int id = blockIdx.x * 256 + threadIdx.x;    // 6*16384
    int m = id >> 14, e = id & 16383;
    int n = e >> 7, k = e & 127;
    const float* srcs[6] = {W1b, W2, W3, W11b, W12, W13};
    float v = srcs[m][k * H + n];
    __half h = __float2half_rn(v);
    g_W[m * 32768 + e]         = h;
    g_W[m * 32768 + 16384 + e] = __float2half_rn(v - __half2float(h));
}

// async weight load (512 threads): 4096 x 16B
__device__ __forceinline__ void load_w_async(uint32_t smDst, int tid, int mat) {
    const char* src = (const char*)(g_W + (size_t)mat * 32768);
    #pragma unroll
    for (int it = 0; it < 8; it++) {
        int id = tid + it * 512;
        int hl = id >> 11, j = id & 2047;
        int n = j >> 4, kc = (j & 15) << 3;
        uint32_t dst = smDst + hl * SLAB + (uint32_t)((n * LDA + kc) * 2);
        asm volatile("cp.async.cg.shared.global [%0], [%1], 16;"
                     :: "r"(dst), "l"(src + (size_t)id * 16));
    }
}

// 2-pass GEMM (A fp16, W hi+lo): acc[4][8] += A(128x128) x W^T (warp: 32x32)
__device__ __forceinline__ void do_gemm(uint32_t wBase, uint32_t aBase, float acc[4][8],
                                        int rowbase, int colq, int lane) {
    int arow = rowbase + (lane & 15);
    int acol = (lane >> 4) << 3;
    uint32_t aOff = aBase + (uint32_t)((arow * LDA + acol) * 2);
    int nrow = colq * 32 + (lane & 7) + ((lane >> 4) << 3);
    int bcol = ((lane >> 3) & 1) << 3;
    uint32_t bOff = wBase + (uint32_t)((nrow * LDA + bcol) * 2);
    #pragma unroll 1
    for (int pass = 0; pass < 2; pass++) {
        uint32_t bB = bOff + ((pass == 1) ? SLAB : 0);
        #pragma unroll 1
        for (int ks = 0; ks < 8; ks++) {
            uint32_t a0[4], a1[4];
            LDSM4(a0[0], a0[1], a0[2], a0[3], aOff + ks * 32);
            LDSM4(a1[0], a1[1], a1[2], a1[3], aOff + 16 * LDA * 2 + ks * 32);
            #pragma unroll
            for (int ntp = 0; ntp < 2; ntp++) {
                uint32_t b0, b1, b2, b3;
                LDSM4(b0, b1, b2, b3, bB + ntp * 16 * LDA * 2 + ks * 32);
                mma16816(&acc[2 * ntp][0],     a0, b0, b1);
                mma16816(&acc[2 * ntp][4],     a1, b0, b1);
                mma16816(&acc[2 * ntp + 1][0], a0, b2, b3);
                mma16816(&acc[2 * ntp + 1][4], a1, b2, b3);
            }
        }
    }
}

// GELU(acc) -> A slab (fp16), for next layer's input
__device__ __forceinline__ void epi_act(char* sm, float acc[4][8],
                                        int rowbase, int colq, int gid, int tig) {
    #pragma unroll
    for (int nt = 0; nt < 4; nt++) {
        int col = colq * 32 + nt * 8 + 2 * tig;
        #pragma unroll
        for (int q = 0; q < 4; q++) {
            int row = rowbase + q * 8 + gid;
            __half2 h = __floats2half2_rn(gelu_f(acc[nt][q * 2]),
                                          gelu_f(acc[nt][q * 2 + 1]));
            *(uint32_t*)(sm + SM_A + (row * LDA + col) * 2) =
                *reinterpret_cast<uint32_t*>(&h);
        }
    }
}

// ---------------- fused 3-layer MLP over one 128-row tile (512 thr) ----------
// MODE 0: node messages -> masked per-token sums into g_dh (atomic)
// MODE 1: edge update -> +hE residual, row LN, write outE
template <int MODE>
__global__ void __launch_bounds__(512, 1) k_mlp(
    const float* __restrict__ hE, const int* __restrict__ Eidx,
    const float* __restrict__ bias2, const float* __restrict__ bias3,
    const float* __restrict__ lng, const float* __restrict__ lnb,
    const float* __restrict__ mattend, float* __restrict__ outE) {
    extern __shared__ char sm[];
    int*   snbr  = (int*)(sm + SM_NBR);
    float* smask = (float*)(sm + SM_MASK);
    float* sb2   = (float*)(sm + SM_B2);
    float* sb3   = (float*)(sm + SM_B3);
    float* sg    = (float*)(sm + SM_G);
    float* sbe   = (float*)(sm + SM_BE);
    float* spar  = (float*)(sm + SM_PAR);

    int tid = threadIdx.x, wid = tid >> 5, lane = tid & 31;
    int gid = lane >> 2, tig = lane & 3;
    int rowbase = (wid & 3) * 32;
    int colq = wid >> 2;
    int grow0 = blockIdx.x * 128;
    uint32_t smb = smem_u32(sm);

    load_w_async(smb + SM_W0, tid, MODE * 3 + 0);
    CP_COMMIT();

    if (tid < 128) {
        int gr = grow0 + tid;
        int t = gr / KNB;
        snbr[tid] = (t / LSEQ) * LSEQ + Eidx[gr];
        smask[tid] = (MODE == 0) ? mattend[gr] : 0.f;
        sb2[tid] = bias2[tid]; sb3[tid] = bias3[tid];
        sg[tid] = lng[tid];    sbe[tid] = lnb[tid];
    }

    // A <- fp16(hE tile)
    const float4* hE4 = reinterpret_cast<const float4*>(hE + (size_t)grow0 * H);
    #pragma unroll
    for (int it = 0; it < 8; it++) {
        int id = tid + it * 512;
        int rr = id >> 5, c4 = id & 31;
        float4 v = hE4[rr * 32 + c4];
        __half2 h01 = __floats2half2_rn(v.x, v.y);
        __half2 h23 = __floats2half2_rn(v.z, v.w);
        *(uint2*)(sm + SM_A + (rr * LDA + c4 * 4) * 2) =
            make_uint2(*reinterpret_cast<uint32_t*>(&h01),
                       *reinterpret_cast<uint32_t*>(&h23));
    }
    CP_WAIT0();
    __syncthreads();

    float acc[4][8];

    // ---- layer 1: acc init = P_center + P_nbr (exact fp32, from global) ----
    {
        const float* Padd = (MODE == 0) ? g_P1 : g_P11;
        const float* Pnbr = (MODE == 0) ? g_P3 : g_P13;
        int tokv[4], nbv[4];
        #pragma unroll
        for (int q = 0; q < 4; q++) {
            int row = rowbase + q * 8 + gid;
            tokv[q] = (grow0 + row) / KNB;
            nbv[q] = snbr[row];
        }
        #pragma unroll
        for (int nt = 0; nt < 4; nt++) {
            int col = colq * 32 + nt * 8 + 2 * tig;
            #pragma unroll
            for (int q = 0; q < 4; q++) {
                float2 a = *(const float2*)(Padd + (size_t)tokv[q] * H + col);
                float2 b = *(const float2*)(Pnbr + (size_t)nbv[q] * H + col);
                acc[nt][q * 2] = a.x + b.x; acc[nt][q * 2 + 1] = a.y + b.y;
            }
        }
    }
    load_w_async(smb + SM_W1, tid, MODE * 3 + 1);
    CP_COMMIT();
    do_gemm(smb + SM_W0, smb + SM_A, acc, rowbase, colq, lane);
    CP_WAIT0();
    __syncthreads();
    epi_act(sm, acc, rowbase, colq, gid, tig);
    __syncthreads();

    // ---- layer 2 ----
    #pragma unroll
    for (int nt = 0; nt < 4; nt++) {
        int col = colq * 32 + nt * 8 + 2 * tig;
        float b0 = sb2[col], b1 = sb2[col + 1];
        #pragma unroll
        for (int q = 0; q < 4; q++) { acc[nt][q * 2] = b0; acc[nt][q * 2 + 1] = b1; }
    }
    load_w_async(smb + SM_W0, tid, MODE * 3 + 2);
    CP_COMMIT();
    do_gemm(smb + SM_W1, smb + SM_A, acc, rowbase, colq, lane);
    CP_WAIT0();
    __syncthreads();
    epi_act(sm, acc, rowbase, colq, gid, tig);
    __syncthreads();

    // ---- layer 3 ----
    #pragma unroll
    for (int nt = 0; nt < 4; nt++) {
        int col = colq * 32 + nt * 8 + 2 * tig;
        float b0 = sb3[col], b1 = sb3[col + 1];
        #pragma unroll
        for (int q = 0; q < 4; q++) { acc[nt][q * 2] = b0; acc[nt][q * 2 + 1] = b1; }
    }
    do_gemm(smb + SM_W0, smb + SM_A, acc, rowbase, colq, lane);

    if (MODE == 0) {
        // masked values -> W1 region (dead), then per-token column sums
        __syncthreads();
        float* fA = (float*)(sm + SM_W1);
        #pragma unroll
        for (int nt = 0; nt < 4; nt++) {
            int col = colq * 32 + nt * 8 + 2 * tig;
            #pragma unroll
            for (int q = 0; q < 4; q++) {
                int row = rowbase + q * 8 + gid;
                float mk = smask[row];
                *(float2*)(fA + row * STG_LD + col) =
                    make_float2(mk * acc[nt][q * 2], mk * acc[nt][q * 2 + 1]);
            }
        }
        __syncthreads();
        int c = tid & 127, qtr = tid >> 7;
        int t0 = grow0 / KNB;
        for (int tok = t0 + qtr; KNB * tok < grow0 + 128; tok += 4) {
            int r0 = KNB * tok - grow0, r1 = r0 + KNB;
            if (r0 < 0) r0 = 0;
            if (r1 > 128) r1 = 128;
            float s = 0.f;
            for (int rr = r0; rr < r1; rr++) s += fA[rr * STG_LD + c];
            atomicAdd(&g_dh[(size_t)tok * H + c], s);
        }
    } else {
        // residual + per-row LN -> outE
        float sA[4], sB[4];
        #pragma unroll
        for (int q = 0; q < 4; q++) { sA[q] = 0.f; sB[q] = 0.f; }
        #pragma unroll
        for (int nt = 0; nt < 4; nt++) {
            int col = colq * 32 + nt * 8 + 2 * tig;
            #pragma unroll
            for (int q = 0; q < 4; q++) {
                int row = rowbase + q * 8 + gid;
                float2 res = *(const float2*)(hE + (size_t)(grow0 + row) * H + col);
                float x0 = acc[nt][q * 2]     + res.x;
                float x1 = acc[nt][q * 2 + 1] + res.y;
                acc[nt][q * 2] = x0; acc[nt][q * 2 + 1] = x1;
                sA[q] += x0 + x1;
                sB[q] += x0 * x0 + x1 * x1;
            }
        }
        #pragma unroll
        for (int q = 0; q < 4; q++) {
            sA[q] += __shfl_xor_sync(0xffffffffu, sA[q], 1);
            sA[q] += __shfl_xor_sync(0xffffffffu, sA[q], 2);
            sB[q] += __shfl_xor_sync(0xffffffffu, sB[q], 1);
            sB[q] += __shfl_xor_sync(0xffffffffu, sB[q], 2);
        }
        if (tig == 0) {
            #pragma unroll
            for (int q = 0; q < 4; q++) {
                int row = rowbase + q * 8 + gid;
                spar[colq * 128 + row]       = sA[q];
                spar[512 + colq * 128 + row] = sB[q];
            }
        }
        __syncthreads();
        float mV = 0.f, rV = 0.f;
        if (tid < 128) {
            float ss  = spar[tid] + spar[128 + tid] + spar[256 + tid] + spar[384 + tid];
            float ss2 = spar[512 + tid] + spar[640 + tid] + spar[768 + tid] + spar[896 + tid];
            mV = ss * (1.f / H);
            rV = rsqrtf(ss2 * (1.f / H) - mV * mV + 1e-5f);
        }
        __syncthreads();
        if (tid < 128) { spar[tid] = mV; spar[128 + tid] = rV; }
        __syncthreads();
        #pragma unroll
        for (int nt = 0; nt < 4; nt++) {
            int col = colq * 32 + nt * 8 + 2 * tig;
            float g0 = sg[col], g1 = sg[col + 1];
            float e0 = sbe[col], e1 = sbe[col + 1];
            #pragma unroll
            for (int q = 0; q < 4; q++) {
                int row = rowbase + q * 8 + gid;
                float m = spar[row], rs = spar[128 + row];
                float2 y;
                y.x = g0 * (acc[nt][q * 2]     - m) * rs + e0;
                y.y = g1 * (acc[nt][q * 2 + 1] - m) * rs + e1;
                *(float2*)(outE + (size_t)(grow0 + row) * H + col) = y;
            }
        }
    }
}

// ---------------- fp32 helpers for pre / ffn ----------------
template<int ROWS, int K4>
__device__ __forceinline__ void gemm_acc(float* acc, const float* A,
                                         const float* __restrict__ W,
                                         int n, int ldw) {
    const float4* A4 = reinterpret_cast<const float4*>(A);
    #pragma unroll 1
    for (int k4 = 0; k4 < K4; k4++) {
        const float* wp = W + (k4 * 4) * ldw + n;
        float w0 = wp[0], w1 = wp[ldw], w2 = wp[2 * ldw], w3 = wp[3 * ldw];
        #pragma unroll
        for (int rr = 0; rr < ROWS; rr++) {
            float4 a = A4[rr * K4 + k4];
            acc[rr] = fmaf(a.x, w0, acc[rr]);
            acc[rr] = fmaf(a.y, w1, acc[rr]);
            acc[rr] = fmaf(a.z, w2, acc[rr]);
            acc[rr] = fmaf(a.w, w3, acc[rr]);
        }
    }
}

__global__ void __launch_bounds__(128) k_pre(const float* __restrict__ hV,
                                             const float* __restrict__ W1,
                                             const float* __restrict__ b1,
                                             int ntok) {
    for (int i = blockIdx.x * 128 + threadIdx.x; i < ntok * H; i += gridDim.x * 128)
        g_dh[i] = 0.f;
    extern __shared__ float smf[];
    float* w1a = smf;
    float* w1c = smf + H * H;
    float* rows = smf + 2 * H * H;
    int tid = threadIdx.x;
    for (int i = tid; i < H * H; i += 128) {
        w1a[i] = W1[i];
        w1c[i] = W1[2 * H * H + i];
    }
    int t0 = blockIdx.x * 32;
    for (int i = tid; i < 32 * H; i += 128) rows[i] = hV[(size_t)t0 * H + i];
    __syncthreads();
    float bn = b1[tid];
    for (int rr = 0; rr < 32; rr++) {
        float a1 = bn, a3 = 0.f;
        const float4* rv = reinterpret_cast<const float4*>(rows + rr * H);
        #pragma unroll 8
        for (int k4 = 0; k4 < 32; k4++) {
            float4 v = rv[k4];
            int k = k4 * 4;
            a1 = fmaf(v.x, w1a[(k+0)*H+tid], a1); a1 = fmaf(v.y, w1a[(k+1)*H+tid], a1);
            a1 = fmaf(v.z, w1a[(k+2)*H+tid], a1); a1 = fmaf(v.w, w1a[(k+3)*H+tid], a1);
            a3 = fmaf(v.x, w1c[(k+0)*H+tid], a3); a3 = fmaf(v.y, w1c[(k+1)*H+tid], a3);
            a3 = fmaf(v.z, w1c[(k+2)*H+tid], a3); a3 = fmaf(v.w, w1c[(k+3)*H+tid], a3);
        }
        g_P1[(size_t)(t0+rr)*H+tid] = a1;
        g_P3[(size_t)(t0+rr)*H+tid] = a3;
    }
}

// FFN with fused LN1 head; 32 tokens/block, 512 threads (16 warps) for latency
__global__ void __launch_bounds__(512, 1) k_ffn(
    const float* __restrict__ hV,    const float* __restrict__ maskV,
    const float* __restrict__ g1,    const float* __restrict__ be1,
    const float* __restrict__ W_in,  const float* __restrict__ b_in,
    const float* __restrict__ W_out, const float* __restrict__ b_out,
    const float* __restrict__ g2,    const float* __restrict__ be2,
    const float* __restrict__ W11,   const float* __restrict__ b11,
    float* __restrict__ outV) {
    extern __shared__ float smf[];
    float* sX   = smf;               // 32*H
    float* sHid = smf + 32 * H;      // 32*512
    float* sMk  = sHid + 32 * 512;   // 32
    int tid = threadIdx.x;
    int t0 = blockIdx.x * 32;
    int col = tid & 127, qtr = tid >> 7;   // 4 row-quarters of 8 rows
    int warp = tid >> 5, lane = tid & 31;

    // LN1 fused: x = hV + g_dh/30, per-row LN -> sX (32 rows, 16 warps)
    for (int rr = warp; rr < 32; rr += 16) {
        size_t base = (size_t)(t0 + rr) * H;
        float v[4];
        #pragma unroll
        for (int j = 0; j < 4; j++) {
            int n = lane + 32 * j;
            v[j] = hV[base + n] + g_dh[base + n] * (1.f / 30.f);
        }
        float s = v[0]+v[1]+v[2]+v[3];
        float s2 = v[0]*v[0]+v[1]*v[1]+v[2]*v[2]+v[3]*v[3];
        #pragma unroll
        for (int o = 16; o; o >>= 1) {
            s  += __shfl_xor_sync(0xffffffffu, s,  o);
            s2 += __shfl_xor_sync(0xffffffffu, s2, o);
        }
        float m = s * (1.f/H);
        float rs = rsqrtf(s2 * (1.f/H) - m*m + 1e-5f);
        #pragma unroll
        for (int j = 0; j < 4; j++) {
            int n = lane + 32 * j;
            sX[rr * H + n] = g1[n] * (v[j] - m) * rs + be1[n];
        }
    }
    if (tid < 32) sMk[tid] = maskV[t0 + tid];
    __syncthreads();

    // hidden layer: 512 cols, ONE col per thread, 32 rows each
    {
        float acc[32];
        float bi = b_in[tid];
        #pragma unroll
        for (int rr = 0; rr < 32; rr++) acc[rr] = bi;
        gemm_acc<32, 32>(acc, sX, W_in, tid, 512);
        #pragma unroll
        for (int rr = 0; rr < 32; rr++) sHid[rr * 512 + tid] = gelu_f(acc[rr]);
    }
    __syncthreads();

    // output layer + residual: 8 rows per quarter
    {
        float acc[8];
        float bo = b_out[col];
        #pragma unroll
        for (int rr = 0; rr < 8; rr++) acc[rr] = bo;
        gemm_acc<8, 128>(acc, sHid + qtr * 8 * 512, W_out, col, H);
        #pragma unroll
        for (int rr = 0; rr < 8; rr++)
            acc[rr] += sX[(qtr * 8 + rr) * H + col];
        __syncthreads();
        #pragma unroll
        for (int rr = 0; rr < 8; rr++)
            sHid[(qtr * 8 + rr) * H + col] = acc[rr];
    }
    __syncthreads();

    // per-row LN2 + mask (16 warps, 2 rows each)
    for (int rr = warp; rr < 32; rr += 16) {
        const float* row = sHid + rr * H;
        float v[4] = { row[lane], row[lane+32], row[lane+64], row[lane+96] };
        float s = v[0]+v[1]+v[2]+v[3];
        float s2 = v[0]*v[0]+v[1]*v[1]+v[2]*v[2]+v[3]*v[3];
        #pragma unroll
        for (int o = 16; o; o >>= 1) {
            s  += __shfl_xor_sync(0xffffffffu, s,  o);
            s2 += __shfl_xor_sync(0xffffffffu, s2, o);
        }
        float m = s * (1.f/H);
        float rs = rsqrtf(s2 * (1.f/H) - m*m + 1e-5f);
        float mk = sMk[rr];
        #pragma unroll
        for (int j = 0; j < 4; j++) {
            int n = lane + 32*j;
            float y = mk * (g2[n]*(v[j]-m)*rs + be2[n]);
            outV[(size_t)(t0+rr)*H + n] = y;
            sX[rr*H + n] = y;
        }
    }
    __syncthreads();

    // P11 / P13 precompute: 8 rows per quarter
    {
        float acc2[8];
        float bb = b11[col];
        #pragma unroll
        for (int rr = 0; rr < 8; rr++) acc2[rr] = bb;
        gemm_acc<8, 32>(acc2, sX + qtr * 8 * H, W11, col, H);
        #pragma unroll
        for (int rr = 0; rr < 8; rr++)
            g_P11[(size_t)(t0 + qtr * 8 + rr) * H + col] = acc2[rr];
        #pragma unroll
        for (int rr = 0; rr < 8; rr++) acc2[rr] = 0.f;
        gemm_acc<8, 32>(acc2, sX + qtr * 8 * H, W11 + 2 * H * H, col, H);
        #pragma unroll
        for (int rr = 0; rr < 8; rr++)
            g_P13[(size_t)(t0 + qtr * 8 + rr) * H + col] = acc2[rr];
    }
}

// ---------------------------------------------------------------------------
extern "C" void kernel_launch(void* const* d_in, const int* in_sizes, int n_in,
                              void* d_out, int out_size) {
    const float* hV    = (const float*)d_in[0];
    const float* hE    = (const float*)d_in[1];
    const int*   Eidx  = (const int*)  d_in[2];
    const float* maskV = (const float*)d_in[3];
    const float* matt  = (const float*)d_in[4];
    const float* W1    = (const float*)d_in[5];
    const float* b1    = (const float*)d_in[6];
    const float* W2    = (const float*)d_in[7];
    const float* b2    = (const float*)d_in[8];
    const float* W3    = (const float*)d_in[9];
    const float* b3    = (const float*)d_in[10];
    const float* W11   = (const float*)d_in[11];
    const float* b11   = (const float*)d_in[12];
    const float* W12   = (const float*)d_in[13];
    const float* b12   = (const float*)d_in[14];
    const float* W13   = (const float*)d_in[15];
    const float* b13   = (const float*)d_in[16];
    const float* g1    = (const float*)d_in[17];
    const float* be1   = (const float*)d_in[18];
    const float* g2    = (const float*)d_in[19];
    const float* be2   = (const float*)d_in[20];
    const float* g3    = (const float*)d_in[21];
    const float* be3   = (const float*)d_in[22];
    const float* W_in  = (const float*)d_in[23];
    const float* b_in  = (const float*)d_in[24];
    const float* W_out = (const float*)d_in[25];
    const float* b_out = (const float*)d_in[26];

    int ntok = in_sizes[3];

    size_t smemP = (size_t)(2 * H * H + 32 * H) * sizeof(float);
    size_t smemB = (size_t)(32 * H + 32 * 512 + 64) * sizeof(float);

    cudaFuncSetAttribute(k_pre,    cudaFuncAttributeMaxDynamicSharedMemorySize, (int)smemP);
    cudaFuncSetAttribute(k_ffn,    cudaFuncAttributeMaxDynamicSharedMemorySize, (int)smemB);
    cudaFuncSetAttribute(k_mlp<0>, cudaFuncAttributeMaxDynamicSharedMemorySize, SMEM_MLP);
    cudaFuncSetAttribute(k_mlp<1>, cudaFuncAttributeMaxDynamicSharedMemorySize, SMEM_MLP);

    float* outV = (float*)d_out;
    float* outE = outV + (size_t)ntok * H;
    int ntile = ntok * KNB / 128;

    k_wprep<<< 6 * 16384 / 256, 256 >>>(W1 + H * H, W2, W3, W11 + H * H, W12, W13);
    k_pre  <<< ntok / 32, 128, smemP >>>(hV, W1, b1, ntok);
    k_mlp<0><<< ntile, 512, SMEM_MLP >>>(hE, Eidx, b2, b3, g1, be1, matt, outE);
    k_ffn  <<< ntok / 32, 512, smemB >>>(hV, maskV, g1, be1, W_in, b_in, W_out, b_out,
                                         g2, be2, W11, b11, outV);
    k_mlp<1><<< ntile, 512, SMEM_MLP >>>(hE, Eidx, b12, b13, g3, be3, matt, outE);
}